// round 11
// baseline (speedup 1.0000x reference)
#include <cuda_runtime.h>
#include <math.h>

#define BB 32
#define GG 36
#define AA 5
#define TT 32
#define NCELL (BB*GG*GG*AA)       /* 207360 */
#define NVEC  (NCELL*5/4)         /* 259200 float4 */
#define IMGSZ 288.0f

#define NBLK 148
#define NTHR 256
#define NW   (NTHR/32)            /* 8 warps */
#define TOT  (NBLK*NTHR)          /* 37888 */
#define SETUP_BLOCKS 128          /* 4 blocks per batch, 8 obj warps each */

// conf2_all accumulator (single, low-traffic: 148 adds)
__device__ double d_acc0;
// per-batch obj accumulators, 256B stride/batch -> spread over L2 lines
// [b][0]=conf2_obj [b][1]=conf1_obj [b][2]=loc [b][3]=nme [b][4]=count
__device__ double d_bacc[BB][32];
__device__ int    d_done;

__device__ __forceinline__ float smooth_l1(float d) {
    float ad = fabsf(d);
    return (ad < 1.0f) ? 0.5f * d * d : ad - 0.5f;
}

// float4 #i holds a conf element at slot k=(i+4)%5 when k<=3
__device__ __forceinline__ float conf_sq(float4 v, int i) {
    int k = (i + 4) % 5;
    float c = (k == 0) ? v.x : (k == 1) ? v.y : (k == 2) ? v.z : (k == 3) ? v.w : 0.0f;
    return c * c;
}

__device__ __forceinline__ int compute_cell(int i, const float* __restrict__ bt) {
    const float* r = bt + (size_t)i * 5;
    float x = r[0], y = r[1], w = r[2], h = r[3], c4 = r[4];
    bool valid = (x + y + w + h + c4) != 0.0f;
    int gi = (int)(x * (float)GG);
    int gj = (int)(y * (float)GG);
    if (!valid || gi < 0 || gi >= GG || gj < 0 || gj >= GG) return -1;

    float gx1 = (x - w * 0.5f) * IMGSZ;
    float gx2 = (x + w * 0.5f) * IMGSZ;
    float gy1 = (y - h * 0.5f) * IMGSZ;
    float gy2 = (y + h * 0.5f) * IMGSZ;
    float area_g = (gx2 - gx1 + 1.0f) * (gy2 - gy1 + 1.0f);

    float acx = (0.5f + (float)gi) / (float)GG;
    float acy = (0.5f + (float)gj) / (float)GG;

    const float aw[AA] = {0.24f, 0.12f, 0.08f, 0.28f, 0.15f};
    int best = 0;
    float best_iou = -1e30f;
#pragma unroll
    for (int a = 0; a < AA; a++) {
        float ax1 = (acx - aw[a] * 0.5f) * IMGSZ;
        float ax2 = (acx + aw[a] * 0.5f) * IMGSZ;
        float ay1 = (acy - aw[a] * 0.5f) * IMGSZ;
        float ay2 = (acy + aw[a] * 0.5f) * IMGSZ;
        float ix1 = fmaxf(gx1, ax1);
        float iy1 = fmaxf(gy1, ay1);
        float ix2 = fminf(gx2, ax2);
        float iy2 = fminf(gy2, ay2);
        float inter  = (ix2 - ix1 + 1.0f) * (iy2 - iy1 + 1.0f);
        float area_a = (ax2 - ax1 + 1.0f) * (ay2 - ay1 + 1.0f);
        float iou = inter / (area_g + area_a - inter + 1e-16f);
        if (iou > best_iou) { best_iou = iou; best = a; }   // first-max argmax
    }
    int b = i / TT;
    return ((b * GG + gj) * GG + gi) * AA + best;
}

__global__ void __launch_bounds__(NTHR)
fused_kernel(const float* __restrict__ bp,
             const float* __restrict__ lmp,
             const float* __restrict__ bt,
             const float* __restrict__ lmt,
             float* __restrict__ out) {
    int lane = threadIdx.x & 31;
    int wid  = threadIdx.x >> 5;
    int tid  = blockIdx.x * NTHR + threadIdx.x;

    bool setup_blk = (blockIdx.x < SETUP_BLOCKS);
    int b = blockIdx.x >> 2;
    int q = blockIdx.x & 3;
    int t = q * NW + wid;              // this warp's target slot (0..31)
    int btid = b * TT + t;

    // ---- issue ALL index-known loads up front (MLP 7 on the conf stream) ----
    const float4* bp4 = (const float4*)bp;
    float4 v0 = bp4[tid];
    float4 v1 = bp4[tid +     TOT];
    float4 v2 = bp4[tid + 2 * TOT];
    float4 v3 = bp4[tid + 3 * TOT];
    float4 v4 = bp4[tid + 4 * TOT];
    float4 v5 = bp4[tid + 5 * TOT];    // 5*37888+37887 = 227327 < 259200
    int i6 = tid + 6 * TOT;
    bool has7 = (i6 < NVEC);
    float4 v6;
    if (has7) v6 = bp4[i6];

    float2 a0, a1, a2;
    float r0, r1, r2, r3;
    bool extra = (lane < 4);
    if (setup_blk) {
        const float2* lt = (const float2*)(lmt + (size_t)btid * 136);
        a0 = lt[lane];
        a1 = lt[lane + 32];
        if (extra) a2 = lt[lane + 64];
        if (lane == 0) {
            const float* r = bt + (size_t)btid * 5;
            r0 = r[0]; r1 = r[1]; r2 = r[2]; r3 = r[3];
        }
    }

    // ---- per-warp cell table + dedupe (no smem, no __syncthreads) ----
    int myCell = -1;
    bool myWin = false;
    if (setup_blk) {
        int cell = compute_cell(b * TT + lane, bt);            // lane == t'
        unsigned m = __match_any_sync(0xffffffffu, cell);
        bool win = (cell >= 0) && ((31 - __clz(m)) == lane);   // last t wins
        unsigned wm = __ballot_sync(0xffffffffu, win);
        myCell = __shfl_sync(0xffffffffu, cell, t);
        myWin  = (wm >> t) & 1u;
    }

    // ---- dependent obj loads (issued ASAP once cell is known) ----
    float2 p0, p1, p2;
    float pb0, pb1, pb2, pb3, pb4;
    if (setup_blk && myWin) {
        const float2* lp = (const float2*)(lmp + (size_t)myCell * 136);
        p0 = lp[lane];
        p1 = lp[lane + 32];
        if (extra) p2 = lp[lane + 64];
        if (lane == 0) {
            const float* p = bp + (size_t)myCell * 5;
            pb0 = p[0]; pb1 = p[1]; pb2 = p[2]; pb3 = p[3]; pb4 = p[4];
        }
    }

    // ---- conf^2 (overlaps with obj-load latency) ----
    float cs = conf_sq(v0, tid)
             + conf_sq(v1, tid +     TOT)
             + conf_sq(v2, tid + 2 * TOT)
             + conf_sq(v3, tid + 3 * TOT)
             + conf_sq(v4, tid + 4 * TOT)
             + conf_sq(v5, tid + 5 * TOT);
    if (has7) cs += conf_sq(v6, i6);

    // ---- obj losses: per-batch spread atomics (<=32 adds per address) ----
    if (setup_blk && myWin) {
        float dx0 = a0.x - p0.x, dy0 = a0.y - p0.y;
        float dx1 = a1.x - p1.x, dy1 = a1.y - p1.y;
        float s = sqrtf(dx0 * dx0 + dy0 * dy0) + sqrtf(dx1 * dx1 + dy1 * dy1);
        if (extra) {
            float dx2 = a2.x - p2.x, dy2 = a2.y - p2.y;
            s += sqrtf(dx2 * dx2 + dy2 * dy2);
        }
#pragma unroll
        for (int o = 16; o > 0; o >>= 1)
            s += __shfl_down_sync(0xffffffffu, s, o);

        if (lane == 0) {
            float l0 = log1pf(r0);
            float l1 = log1pf(r1);
            float l2 = log1pf(r2);
            float l3 = log1pf(r3);

            float loc = smooth_l1(pb0 - l0) + smooth_l1(pb1 - l1)
                      + smooth_l1(pb2 - l2) + smooth_l1(pb3 - l3);
            float cm1 = pb4 - 1.0f;
            float nf  = sqrtf(l2 * l3);

            atomicAdd(&d_bacc[b][0], (double)pb4 * (double)pb4);
            atomicAdd(&d_bacc[b][1], (double)cm1 * (double)cm1);
            atomicAdd(&d_bacc[b][2], (double)loc);
            atomicAdd(&d_bacc[b][3], (double)(s / nf));
            atomicAdd(&d_bacc[b][4], 1.0);
            __threadfence();
        }
    }

    // ---- tail: block-reduce conf2_all, ticket, warp-parallel finalize ----
    {
        double x = (double)cs;
#pragma unroll
        for (int o = 16; o > 0; o >>= 1)
            x += __shfl_down_sync(0xffffffffu, x, o);
        __shared__ double sh[NW];
        if (lane == 0) sh[wid] = x;
        __syncthreads();
        if (wid == 0) {
            int last = 0;
            if (lane == 0) {
                double sum = sh[0];
#pragma unroll
                for (int k = 1; k < NW; k++) sum += sh[k];
                atomicAdd(&d_acc0, sum);
                __threadfence();
                last = (atomicAdd(&d_done, 1) == NBLK - 1) ? 1 : 0;
            }
            last = __shfl_sync(0xffffffffu, last, 0);
            if (last) {
                __threadfence();   // make all partials visible
                // lane = batch: load this batch's 5 obj sums
                double r0d = d_bacc[lane][0];
                double r1d = d_bacc[lane][1];
                double r2d = d_bacc[lane][2];
                double r3d = d_bacc[lane][3];
                double r4d = d_bacc[lane][4];
#pragma unroll
                for (int o = 16; o > 0; o >>= 1) {
                    r0d += __shfl_down_sync(0xffffffffu, r0d, o);
                    r1d += __shfl_down_sync(0xffffffffu, r1d, o);
                    r2d += __shfl_down_sync(0xffffffffu, r2d, o);
                    r3d += __shfl_down_sync(0xffffffffu, r3d, o);
                    r4d += __shfl_down_sync(0xffffffffu, r4d, o);
                }
                // reset this batch's row for the next graph replay
                d_bacc[lane][0] = 0.0;
                d_bacc[lane][1] = 0.0;
                d_bacc[lane][2] = 0.0;
                d_bacc[lane][3] = 0.0;
                d_bacc[lane][4] = 0.0;
                if (lane == 0) {
                    double conf2_all = d_acc0;
                    double conf2_obj = r0d;
                    double conf1_obj = r1d;
                    double loc_sum   = r2d;
                    double nme_sum   = r3d;
                    double cnt       = r4d;

                    double n_obj   = fmax(cnt, 1.0);
                    double n_noobj = fmax((double)NCELL - cnt, 1.0);

                    out[0] = (float)(2.0 * nme_sum / (68.0 * n_obj));
                    out[1] = (float)(5.0 * loc_sum / (n_obj * 4.0));
                    out[2] = (float)(0.5 * (conf2_all - conf2_obj) / n_noobj
                                     + conf1_obj / n_obj);

                    d_acc0 = 0.0;
                    __threadfence();
                    d_done = 0;
                }
            }
        }
    }
}

extern "C" void kernel_launch(void* const* d_in, const int* in_sizes, int n_in,
                              void* d_out, int out_size) {
    const float* bbox_pred = (const float*)d_in[0];   // (32,36,36,5,5)
    const float* lm_pred   = (const float*)d_in[1];   // (32,36,36,5,68,2)
    const float* bbox_tgt  = (const float*)d_in[2];   // (32,32,5)
    const float* lm_tgt    = (const float*)d_in[3];   // (32,32,68,2)
    float* out = (float*)d_out;

    fused_kernel<<<NBLK, NTHR>>>(bbox_pred, lm_pred, bbox_tgt, lm_tgt, out);
}

// round 12
// speedup vs baseline: 1.0173x; 1.0173x over previous
#include <cuda_runtime.h>
#include <math.h>

#define BB 32
#define GG 36
#define AA 5
#define TT 32
#define NCELL (BB*GG*GG*AA)       /* 207360 */
#define NVEC  (NCELL*5/4)         /* 259200 float4 */
#define IMGSZ 288.0f

#define NBLK 592
#define NTHR 256
#define NW   (NTHR/32)            /* 8 warps */
#define TOT  (NBLK*NTHR)          /* 151552 */
#define SETUP_BLOCKS 128          /* 4 blocks per batch, 8 obj warps each */

// conf2_all accumulator (single, low-traffic: 592 adds)
__device__ double d_acc0;
// per-batch obj accumulators, 256B stride/batch -> spread over L2 lines
// [b][0]=conf2_obj [b][1]=conf1_obj [b][2]=loc [b][3]=nme [b][4]=count
__device__ double d_bacc[BB][32];
__device__ int    d_done;

__device__ __forceinline__ float smooth_l1(float d) {
    float ad = fabsf(d);
    return (ad < 1.0f) ? 0.5f * d * d : ad - 0.5f;
}

// float4 #i holds a conf element at slot k=(i+4)%5 when k<=3
__device__ __forceinline__ float conf_sq(float4 v, int i) {
    int k = (i + 4) % 5;
    float c = (k == 0) ? v.x : (k == 1) ? v.y : (k == 2) ? v.z : (k == 3) ? v.w : 0.0f;
    return c * c;
}

__device__ __forceinline__ int compute_cell(int i, const float* __restrict__ bt) {
    const float* r = bt + (size_t)i * 5;
    float x = r[0], y = r[1], w = r[2], h = r[3], c4 = r[4];
    bool valid = (x + y + w + h + c4) != 0.0f;
    int gi = (int)(x * (float)GG);
    int gj = (int)(y * (float)GG);
    if (!valid || gi < 0 || gi >= GG || gj < 0 || gj >= GG) return -1;

    float gx1 = (x - w * 0.5f) * IMGSZ;
    float gx2 = (x + w * 0.5f) * IMGSZ;
    float gy1 = (y - h * 0.5f) * IMGSZ;
    float gy2 = (y + h * 0.5f) * IMGSZ;
    float area_g = (gx2 - gx1 + 1.0f) * (gy2 - gy1 + 1.0f);

    float acx = (0.5f + (float)gi) / (float)GG;
    float acy = (0.5f + (float)gj) / (float)GG;

    const float aw[AA] = {0.24f, 0.12f, 0.08f, 0.28f, 0.15f};
    int best = 0;
    float best_iou = -1e30f;
#pragma unroll
    for (int a = 0; a < AA; a++) {
        float ax1 = (acx - aw[a] * 0.5f) * IMGSZ;
        float ax2 = (acx + aw[a] * 0.5f) * IMGSZ;
        float ay1 = (acy - aw[a] * 0.5f) * IMGSZ;
        float ay2 = (acy + aw[a] * 0.5f) * IMGSZ;
        float ix1 = fmaxf(gx1, ax1);
        float iy1 = fmaxf(gy1, ay1);
        float ix2 = fminf(gx2, ax2);
        float iy2 = fminf(gy2, ay2);
        float inter  = (ix2 - ix1 + 1.0f) * (iy2 - iy1 + 1.0f);
        float area_a = (ax2 - ax1 + 1.0f) * (ay2 - ay1 + 1.0f);
        float iou = inter / (area_g + area_a - inter + 1e-16f);
        if (iou > best_iou) { best_iou = iou; best = a; }   // first-max argmax
    }
    int b = i / TT;
    return ((b * GG + gj) * GG + gi) * AA + best;
}

__global__ void __launch_bounds__(NTHR)
fused_kernel(const float* __restrict__ bp,
             const float* __restrict__ lmp,
             const float* __restrict__ bt,
             const float* __restrict__ lmt,
             float* __restrict__ out) {
    int lane = threadIdx.x & 31;
    int wid  = threadIdx.x >> 5;
    int tid  = blockIdx.x * NTHR + threadIdx.x;

    bool setup_blk = (blockIdx.x < SETUP_BLOCKS);
    int b = blockIdx.x >> 2;
    int q = blockIdx.x & 3;
    int t = q * NW + wid;              // this warp's target slot (0..31)
    int btid = b * TT + t;

    // ---- issue ALL index-known loads up front ----
    const float4* bp4 = (const float4*)bp;
    float4 v0 = bp4[tid];              //  tid < 151552 < 259200
    int i1 = tid + TOT;
    bool has2 = (i1 < NVEC);
    float4 v1;
    if (has2) v1 = bp4[i1];

    float2 a0, a1, a2;
    float r0, r1, r2, r3;
    bool extra = (lane < 4);
    if (setup_blk) {
        const float2* lt = (const float2*)(lmt + (size_t)btid * 136);
        a0 = lt[lane];
        a1 = lt[lane + 32];
        if (extra) a2 = lt[lane + 64];
        if (lane == 0) {
            const float* r = bt + (size_t)btid * 5;
            r0 = r[0]; r1 = r[1]; r2 = r[2]; r3 = r[3];
        }
    }

    // ---- per-warp cell table + dedupe (no smem, no __syncthreads) ----
    int myCell = -1;
    bool myWin = false;
    if (setup_blk) {
        int cell = compute_cell(b * TT + lane, bt);            // lane == t'
        unsigned m = __match_any_sync(0xffffffffu, cell);
        bool win = (cell >= 0) && ((31 - __clz(m)) == lane);   // last t wins
        unsigned wm = __ballot_sync(0xffffffffu, win);
        myCell = __shfl_sync(0xffffffffu, cell, t);
        myWin  = (wm >> t) & 1u;
    }

    // ---- dependent obj loads (issued ASAP once cell is known) ----
    float2 p0, p1, p2;
    float pb0, pb1, pb2, pb3, pb4;
    if (setup_blk && myWin) {
        const float2* lp = (const float2*)(lmp + (size_t)myCell * 136);
        p0 = lp[lane];
        p1 = lp[lane + 32];
        if (extra) p2 = lp[lane + 64];
        if (lane == 0) {
            const float* p = bp + (size_t)myCell * 5;
            pb0 = p[0]; pb1 = p[1]; pb2 = p[2]; pb3 = p[3]; pb4 = p[4];
        }
    }

    // ---- conf^2 (overlaps with obj-load latency) ----
    float cs = conf_sq(v0, tid);
    if (has2) cs += conf_sq(v1, i1);

    // ---- obj losses: per-batch spread atomics (<=32 adds per address) ----
    if (setup_blk && myWin) {
        float dx0 = a0.x - p0.x, dy0 = a0.y - p0.y;
        float dx1 = a1.x - p1.x, dy1 = a1.y - p1.y;
        float s = sqrtf(dx0 * dx0 + dy0 * dy0) + sqrtf(dx1 * dx1 + dy1 * dy1);
        if (extra) {
            float dx2 = a2.x - p2.x, dy2 = a2.y - p2.y;
            s += sqrtf(dx2 * dx2 + dy2 * dy2);
        }
#pragma unroll
        for (int o = 16; o > 0; o >>= 1)
            s += __shfl_down_sync(0xffffffffu, s, o);

        if (lane == 0) {
            float l0 = log1pf(r0);
            float l1 = log1pf(r1);
            float l2 = log1pf(r2);
            float l3 = log1pf(r3);

            float loc = smooth_l1(pb0 - l0) + smooth_l1(pb1 - l1)
                      + smooth_l1(pb2 - l2) + smooth_l1(pb3 - l3);
            float cm1 = pb4 - 1.0f;
            float nf  = sqrtf(l2 * l3);

            atomicAdd(&d_bacc[b][0], (double)pb4 * (double)pb4);
            atomicAdd(&d_bacc[b][1], (double)cm1 * (double)cm1);
            atomicAdd(&d_bacc[b][2], (double)loc);
            atomicAdd(&d_bacc[b][3], (double)(s / nf));
            atomicAdd(&d_bacc[b][4], 1.0);
            __threadfence();
        }
    }

    // ---- tail: block-reduce conf2_all, ticket, warp-parallel finalize ----
    {
        double x = (double)cs;
#pragma unroll
        for (int o = 16; o > 0; o >>= 1)
            x += __shfl_down_sync(0xffffffffu, x, o);
        __shared__ double sh[NW];
        if (lane == 0) sh[wid] = x;
        __syncthreads();
        if (wid == 0) {
            int last = 0;
            if (lane == 0) {
                double sum = sh[0];
#pragma unroll
                for (int k = 1; k < NW; k++) sum += sh[k];
                atomicAdd(&d_acc0, sum);
                __threadfence();
                last = (atomicAdd(&d_done, 1) == NBLK - 1) ? 1 : 0;
            }
            last = __shfl_sync(0xffffffffu, last, 0);
            if (last) {
                __threadfence();   // make all partials visible
                // lane = batch: load this batch's 5 obj sums
                double r0d = d_bacc[lane][0];
                double r1d = d_bacc[lane][1];
                double r2d = d_bacc[lane][2];
                double r3d = d_bacc[lane][3];
                double r4d = d_bacc[lane][4];
#pragma unroll
                for (int o = 16; o > 0; o >>= 1) {
                    r0d += __shfl_down_sync(0xffffffffu, r0d, o);
                    r1d += __shfl_down_sync(0xffffffffu, r1d, o);
                    r2d += __shfl_down_sync(0xffffffffu, r2d, o);
                    r3d += __shfl_down_sync(0xffffffffu, r3d, o);
                    r4d += __shfl_down_sync(0xffffffffu, r4d, o);
                }
                // reset this batch's row for the next graph replay
                d_bacc[lane][0] = 0.0;
                d_bacc[lane][1] = 0.0;
                d_bacc[lane][2] = 0.0;
                d_bacc[lane][3] = 0.0;
                d_bacc[lane][4] = 0.0;
                if (lane == 0) {
                    double conf2_all = d_acc0;
                    double conf2_obj = r0d;
                    double conf1_obj = r1d;
                    double loc_sum   = r2d;
                    double nme_sum   = r3d;
                    double cnt       = r4d;

                    double n_obj   = fmax(cnt, 1.0);
                    double n_noobj = fmax((double)NCELL - cnt, 1.0);

                    out[0] = (float)(2.0 * nme_sum / (68.0 * n_obj));
                    out[1] = (float)(5.0 * loc_sum / (n_obj * 4.0));
                    out[2] = (float)(0.5 * (conf2_all - conf2_obj) / n_noobj
                                     + conf1_obj / n_obj);

                    d_acc0 = 0.0;
                    __threadfence();
                    d_done = 0;
                }
            }
        }
    }
}

extern "C" void kernel_launch(void* const* d_in, const int* in_sizes, int n_in,
                              void* d_out, int out_size) {
    const float* bbox_pred = (const float*)d_in[0];   // (32,36,36,5,5)
    const float* lm_pred   = (const float*)d_in[1];   // (32,36,36,5,68,2)
    const float* bbox_tgt  = (const float*)d_in[2];   // (32,32,5)
    const float* lm_tgt    = (const float*)d_in[3];   // (32,32,68,2)
    float* out = (float*)d_out;

    fused_kernel<<<NBLK, NTHR>>>(bbox_pred, lm_pred, bbox_tgt, lm_tgt, out);
}

// round 13
// speedup vs baseline: 1.1572x; 1.1376x over previous
#include <cuda_runtime.h>
#include <math.h>

#define BB 32
#define GG 36
#define AA 5
#define TT 32
#define NCELL (BB*GG*GG*AA)       /* 207360 */
#define NVEC  (NCELL*5/4)         /* 259200 float4 */
#define IMGSZ 288.0f

#define NBLK 296
#define NTHR 256
#define NW   (NTHR/32)            /* 8 warps */
#define TOT  (NBLK*NTHR)          /* 75776 */
#define SETUP_BLOCKS 128          /* 4 blocks per batch, 8 obj warps each */

// conf2_all accumulator (single, low-traffic: 296 adds)
__device__ double d_acc0;
// per-batch obj accumulators, 256B stride/batch -> spread over L2 lines
// [b][0]=conf2_obj [b][1]=conf1_obj [b][2]=loc [b][3]=nme [b][4]=count
__device__ double d_bacc[BB][32];
__device__ int    d_done;

__device__ __forceinline__ float smooth_l1(float d) {
    float ad = fabsf(d);
    return (ad < 1.0f) ? 0.5f * d * d : ad - 0.5f;
}

// float4 #i holds a conf element at slot k=(i+4)%5 when k<=3
__device__ __forceinline__ float conf_sq(float4 v, int i) {
    int k = (i + 4) % 5;
    float c = (k == 0) ? v.x : (k == 1) ? v.y : (k == 2) ? v.z : (k == 3) ? v.w : 0.0f;
    return c * c;
}

__device__ __forceinline__ int compute_cell(int i, const float* __restrict__ bt) {
    const float* r = bt + (size_t)i * 5;
    float x = r[0], y = r[1], w = r[2], h = r[3], c4 = r[4];
    bool valid = (x + y + w + h + c4) != 0.0f;
    int gi = (int)(x * (float)GG);
    int gj = (int)(y * (float)GG);
    if (!valid || gi < 0 || gi >= GG || gj < 0 || gj >= GG) return -1;

    float gx1 = (x - w * 0.5f) * IMGSZ;
    float gx2 = (x + w * 0.5f) * IMGSZ;
    float gy1 = (y - h * 0.5f) * IMGSZ;
    float gy2 = (y + h * 0.5f) * IMGSZ;
    float area_g = (gx2 - gx1 + 1.0f) * (gy2 - gy1 + 1.0f);

    float acx = (0.5f + (float)gi) / (float)GG;
    float acy = (0.5f + (float)gj) / (float)GG;

    const float aw[AA] = {0.24f, 0.12f, 0.08f, 0.28f, 0.15f};
    int best = 0;
    float best_iou = -1e30f;
#pragma unroll
    for (int a = 0; a < AA; a++) {
        float ax1 = (acx - aw[a] * 0.5f) * IMGSZ;
        float ax2 = (acx + aw[a] * 0.5f) * IMGSZ;
        float ay1 = (acy - aw[a] * 0.5f) * IMGSZ;
        float ay2 = (acy + aw[a] * 0.5f) * IMGSZ;
        float ix1 = fmaxf(gx1, ax1);
        float iy1 = fmaxf(gy1, ay1);
        float ix2 = fminf(gx2, ax2);
        float iy2 = fminf(gy2, ay2);
        float inter  = (ix2 - ix1 + 1.0f) * (iy2 - iy1 + 1.0f);
        float area_a = (ax2 - ax1 + 1.0f) * (ay2 - ay1 + 1.0f);
        float iou = inter / (area_g + area_a - inter + 1e-16f);
        if (iou > best_iou) { best_iou = iou; best = a; }   // first-max argmax
    }
    int b = i / TT;
    return ((b * GG + gj) * GG + gi) * AA + best;
}

__global__ void __launch_bounds__(NTHR)
fused_kernel(const float* __restrict__ bp,
             const float* __restrict__ lmp,
             const float* __restrict__ bt,
             const float* __restrict__ lmt,
             float* __restrict__ out) {
    int lane = threadIdx.x & 31;
    int wid  = threadIdx.x >> 5;
    int tid  = blockIdx.x * NTHR + threadIdx.x;

    __shared__ double sh[NW];
    __shared__ double s_out[5];
    __shared__ int    s_last;

    bool setup_blk = (blockIdx.x < SETUP_BLOCKS);
    int b = blockIdx.x >> 2;
    int q = blockIdx.x & 3;
    int t = q * NW + wid;              // this warp's target slot (0..31)
    int btid = b * TT + t;

    // ---- issue ALL index-known loads up front (MLP 4 on the conf stream) ----
    const float4* bp4 = (const float4*)bp;
    float4 va = bp4[tid];              //  < 75776
    float4 vb = bp4[tid + TOT];        //  < 151552
    float4 vc = bp4[tid + 2 * TOT];    //  < 227328 (< 259200)
    int i3 = tid + 3 * TOT;
    bool has4 = (i3 < NVEC);
    float4 vd;
    if (has4) vd = bp4[i3];

    float2 a0, a1, a2;
    float r0, r1, r2, r3;
    bool extra = (lane < 4);
    if (setup_blk) {
        const float2* lt = (const float2*)(lmt + (size_t)btid * 136);
        a0 = lt[lane];
        a1 = lt[lane + 32];
        if (extra) a2 = lt[lane + 64];
        if (lane == 0) {
            const float* r = bt + (size_t)btid * 5;
            r0 = r[0]; r1 = r[1]; r2 = r[2]; r3 = r[3];
        }
    }

    // ---- per-warp cell table + dedupe (no smem, no __syncthreads) ----
    int myCell = -1;
    bool myWin = false;
    if (setup_blk) {
        int cell = compute_cell(b * TT + lane, bt);            // lane == t'
        unsigned m = __match_any_sync(0xffffffffu, cell);
        bool win = (cell >= 0) && ((31 - __clz(m)) == lane);   // last t wins
        unsigned wm = __ballot_sync(0xffffffffu, win);
        myCell = __shfl_sync(0xffffffffu, cell, t);
        myWin  = (wm >> t) & 1u;
    }

    // ---- dependent obj loads (issued ASAP once cell is known) ----
    float2 p0, p1, p2;
    float pb0, pb1, pb2, pb3, pb4;
    if (setup_blk && myWin) {
        const float2* lp = (const float2*)(lmp + (size_t)myCell * 136);
        p0 = lp[lane];
        p1 = lp[lane + 32];
        if (extra) p2 = lp[lane + 64];
        if (lane == 0) {
            const float* p = bp + (size_t)myCell * 5;
            pb0 = p[0]; pb1 = p[1]; pb2 = p[2]; pb3 = p[3]; pb4 = p[4];
        }
    }

    // ---- conf^2 (overlaps with obj-load latency) ----
    float cs = conf_sq(va, tid)
             + conf_sq(vb, tid + TOT)
             + conf_sq(vc, tid + 2 * TOT);
    if (has4) cs += conf_sq(vd, i3);

    // ---- obj losses: per-batch spread atomics (<=32 adds per address) ----
    if (setup_blk && myWin) {
        float dx0 = a0.x - p0.x, dy0 = a0.y - p0.y;
        float dx1 = a1.x - p1.x, dy1 = a1.y - p1.y;
        float s = sqrtf(dx0 * dx0 + dy0 * dy0) + sqrtf(dx1 * dx1 + dy1 * dy1);
        if (extra) {
            float dx2 = a2.x - p2.x, dy2 = a2.y - p2.y;
            s += sqrtf(dx2 * dx2 + dy2 * dy2);
        }
#pragma unroll
        for (int o = 16; o > 0; o >>= 1)
            s += __shfl_down_sync(0xffffffffu, s, o);

        if (lane == 0) {
            float l0 = log1pf(r0);
            float l1 = log1pf(r1);
            float l2 = log1pf(r2);
            float l3 = log1pf(r3);

            float loc = smooth_l1(pb0 - l0) + smooth_l1(pb1 - l1)
                      + smooth_l1(pb2 - l2) + smooth_l1(pb3 - l3);
            float cm1 = pb4 - 1.0f;
            float nf  = sqrtf(l2 * l3);

            atomicAdd(&d_bacc[b][0], (double)pb4 * (double)pb4);
            atomicAdd(&d_bacc[b][1], (double)cm1 * (double)cm1);
            atomicAdd(&d_bacc[b][2], (double)loc);
            atomicAdd(&d_bacc[b][3], (double)(s / nf));
            atomicAdd(&d_bacc[b][4], 1.0);
            __threadfence();
        }
    }

    // ---- tail: float warp-reduce of conf2, ticket, 5-warp finalize ----
    {
        float x = cs;
#pragma unroll
        for (int o = 16; o > 0; o >>= 1)
            x += __shfl_down_sync(0xffffffffu, x, o);
        if (lane == 0) sh[wid] = (double)x;
        __syncthreads();
        if (threadIdx.x == 0) {
            // pairwise tree: 3 dependent DADD levels
            double s01 = sh[0] + sh[1];
            double s23 = sh[2] + sh[3];
            double s45 = sh[4] + sh[5];
            double s67 = sh[6] + sh[7];
            double sum = (s01 + s23) + (s45 + s67);
            atomicAdd(&d_acc0, sum);
            __threadfence();
            s_last = (atomicAdd(&d_done, 1) == NBLK - 1) ? 1 : 0;
        }
        __syncthreads();

        if (s_last) {
            __threadfence();   // make all blocks' partials visible
            // 5 warps in parallel: warp j reduces obj quantity j
            if (wid < 5) {
                double x5 = d_bacc[lane][wid];
#pragma unroll
                for (int o = 16; o > 0; o >>= 1)
                    x5 += __shfl_down_sync(0xffffffffu, x5, o);
                d_bacc[lane][wid] = 0.0;    // reset for next replay
                if (lane == 0) s_out[wid] = x5;
            }
            __syncthreads();
            if (threadIdx.x == 0) {
                double conf2_all = d_acc0;
                double conf2_obj = s_out[0];
                double conf1_obj = s_out[1];
                double loc_sum   = s_out[2];
                double nme_sum   = s_out[3];
                double cnt       = s_out[4];

                double n_obj   = fmax(cnt, 1.0);
                double n_noobj = fmax((double)NCELL - cnt, 1.0);

                out[0] = (float)(2.0 * nme_sum / (68.0 * n_obj));
                out[1] = (float)(5.0 * loc_sum / (n_obj * 4.0));
                out[2] = (float)(0.5 * (conf2_all - conf2_obj) / n_noobj
                                 + conf1_obj / n_obj);

                d_acc0 = 0.0;
                __threadfence();
                d_done = 0;
            }
        }
    }
}

extern "C" void kernel_launch(void* const* d_in, const int* in_sizes, int n_in,
                              void* d_out, int out_size) {
    const float* bbox_pred = (const float*)d_in[0];   // (32,36,36,5,5)
    const float* lm_pred   = (const float*)d_in[1];   // (32,36,36,5,68,2)
    const float* bbox_tgt  = (const float*)d_in[2];   // (32,32,5)
    const float* lm_tgt    = (const float*)d_in[3];   // (32,32,68,2)
    float* out = (float*)d_out;

    fused_kernel<<<NBLK, NTHR>>>(bbox_pred, lm_pred, bbox_tgt, lm_tgt, out);
}

// round 14
// speedup vs baseline: 1.1775x; 1.0175x over previous
#include <cuda_runtime.h>
#include <math.h>

#define BB 32
#define GG 36
#define AA 5
#define TT 32
#define NCELL (BB*GG*GG*AA)       /* 207360 */
#define NVEC  (NCELL*5/4)         /* 259200 float4 */
#define IMGSZ 288.0f

#define NBLK 296
#define NTHR 256
#define NW   (NTHR/32)            /* 8 warps */
#define TOT  (NBLK*NTHR)          /* 75776 */
#define SETUP_BLOCKS 128          /* 4 blocks per batch, 8 obj warps each */

// conf2_all accumulator (single, low-traffic: 296 adds)
__device__ double d_acc0;
// per-batch obj accumulators, 256B stride/batch -> spread over L2 lines
// [b][0]=conf2_obj [b][1]=conf1_obj [b][2]=loc [b][3]=nme [b][4]=count
__device__ double d_bacc[BB][32];
__device__ int    d_done;

__device__ __forceinline__ float smooth_l1(float d) {
    float ad = fabsf(d);
    return (ad < 1.0f) ? 0.5f * d * d : ad - 0.5f;
}

// float4 #i holds a conf element at slot k=(i+4)%5 when k<=3
__device__ __forceinline__ float conf_sq(float4 v, int i) {
    int k = (i + 4) % 5;
    float c = (k == 0) ? v.x : (k == 1) ? v.y : (k == 2) ? v.z : (k == 3) ? v.w : 0.0f;
    return c * c;
}

__device__ __forceinline__ int cell_from_row(float x, float y, float w, float h,
                                             float c4, int b) {
    bool valid = (x + y + w + h + c4) != 0.0f;
    int gi = (int)(x * (float)GG);
    int gj = (int)(y * (float)GG);
    if (!valid || gi < 0 || gi >= GG || gj < 0 || gj >= GG) return -1;

    float gx1 = (x - w * 0.5f) * IMGSZ;
    float gx2 = (x + w * 0.5f) * IMGSZ;
    float gy1 = (y - h * 0.5f) * IMGSZ;
    float gy2 = (y + h * 0.5f) * IMGSZ;
    float area_g = (gx2 - gx1 + 1.0f) * (gy2 - gy1 + 1.0f);

    float acx = (0.5f + (float)gi) / (float)GG;
    float acy = (0.5f + (float)gj) / (float)GG;

    const float aw[AA] = {0.24f, 0.12f, 0.08f, 0.28f, 0.15f};
    int best = 0;
    float best_iou = -1e30f;
#pragma unroll
    for (int a = 0; a < AA; a++) {
        float ax1 = (acx - aw[a] * 0.5f) * IMGSZ;
        float ax2 = (acx + aw[a] * 0.5f) * IMGSZ;
        float ay1 = (acy - aw[a] * 0.5f) * IMGSZ;
        float ay2 = (acy + aw[a] * 0.5f) * IMGSZ;
        float ix1 = fmaxf(gx1, ax1);
        float iy1 = fmaxf(gy1, ay1);
        float ix2 = fminf(gx2, ax2);
        float iy2 = fminf(gy2, ay2);
        float inter  = (ix2 - ix1 + 1.0f) * (iy2 - iy1 + 1.0f);
        float area_a = (ax2 - ax1 + 1.0f) * (ay2 - ay1 + 1.0f);
        float iou = inter / (area_g + area_a - inter + 1e-16f);
        if (iou > best_iou) { best_iou = iou; best = a; }   // first-max argmax
    }
    return ((b * GG + gj) * GG + gi) * AA + best;
}

__global__ void __launch_bounds__(NTHR)
fused_kernel(const float* __restrict__ bp,
             const float* __restrict__ lmp,
             const float* __restrict__ bt,
             const float* __restrict__ lmt,
             float* __restrict__ out) {
    int lane = threadIdx.x & 31;
    int wid  = threadIdx.x >> 5;
    int tid  = blockIdx.x * NTHR + threadIdx.x;

    __shared__ double sh[NW];
    __shared__ double s_out[5];
    __shared__ int    s_last;

    bool setup_blk = (blockIdx.x < SETUP_BLOCKS);
    int b = blockIdx.x >> 2;
    int q = blockIdx.x & 3;
    int t = q * NW + wid;              // this warp's target slot (0..31)
    int btid = b * TT + t;

    const float4* bp4 = (const float4*)bp;
    float4 va, vb, vc, vd;
    int i3 = tid + 3 * TOT;
    bool has4 = (i3 < NVEC);
    bool extra = (lane < 4);

    float cs;
    double o1 = 0.0, o2 = 0.0, o3 = 0.0, o4 = 0.0, o5 = 0.0;

    if (!setup_blk) {
        // ---- non-setup: pure conf stream, issue immediately ----
        va = bp4[tid];
        vb = bp4[tid + TOT];
        vc = bp4[tid + 2 * TOT];
        if (has4) vd = bp4[i3];
        cs = conf_sq(va, tid)
           + conf_sq(vb, tid + TOT)
           + conf_sq(vc, tid + 2 * TOT);
        if (has4) cs += conf_sq(vd, i3);
    } else {
        // ---- setup: CHAIN-CRITICAL loads first ----
        // 1) bt row for this lane's cell computation (lane == t')
        const float* rl = bt + (size_t)(b * TT + lane) * 5;
        float cx = rl[0], cy = rl[1], cw = rl[2], ch = rl[3], cc = rl[4];

        // 2) own-target landmark targets + bt row (index known at entry)
        const float2* lt = (const float2*)(lmt + (size_t)btid * 136);
        float2 a0 = lt[lane];
        float2 a1 = lt[lane + 32];
        float2 a2;
        if (extra) a2 = lt[lane + 64];
        float r0, r1, r2, r3;
        if (lane == 0) {
            const float* r = bt + (size_t)btid * 5;
            r0 = r[0]; r1 = r[1]; r2 = r[2]; r3 = r[3];
        }

        // 3) cell + warp dedupe (last t wins)
        int cell = cell_from_row(cx, cy, cw, ch, cc, b);
        unsigned m = __match_any_sync(0xffffffffu, cell);
        bool win = (cell >= 0) && ((31 - __clz(m)) == lane);
        unsigned wm = __ballot_sync(0xffffffffu, win);
        int myCell = __shfl_sync(0xffffffffu, cell, t);
        bool myWin = (wm >> t) & 1u;

        // 4) dependent obj loads ASAP
        float2 p0, p1, p2;
        float pb0, pb1, pb2, pb3, pb4;
        if (myWin) {
            const float2* lp = (const float2*)(lmp + (size_t)myCell * 136);
            p0 = lp[lane];
            p1 = lp[lane + 32];
            if (extra) p2 = lp[lane + 64];
            if (lane == 0) {
                const float* p = bp + (size_t)myCell * 5;
                pb0 = p[0]; pb1 = p[1]; pb2 = p[2]; pb3 = p[3]; pb4 = p[4];
            }
        }

        // 5) bulk conf loads AFTER the chain (latency hides behind obj round)
        va = bp4[tid];
        vb = bp4[tid + TOT];
        vc = bp4[tid + 2 * TOT];
        if (has4) vd = bp4[i3];

        // 6) conf math (overlaps obj-load latency)
        cs = conf_sq(va, tid)
           + conf_sq(vb, tid + TOT)
           + conf_sq(vc, tid + 2 * TOT);
        if (has4) cs += conf_sq(vd, i3);

        // 7) obj losses
        if (myWin) {
            float dx0 = a0.x - p0.x, dy0 = a0.y - p0.y;
            float dx1 = a1.x - p1.x, dy1 = a1.y - p1.y;
            float s = sqrtf(dx0 * dx0 + dy0 * dy0) + sqrtf(dx1 * dx1 + dy1 * dy1);
            if (extra) {
                float dx2 = a2.x - p2.x, dy2 = a2.y - p2.y;
                s += sqrtf(dx2 * dx2 + dy2 * dy2);
            }
#pragma unroll
            for (int o = 16; o > 0; o >>= 1)
                s += __shfl_down_sync(0xffffffffu, s, o);

            if (lane == 0) {
                float l0 = log1pf(r0);
                float l1 = log1pf(r1);
                float l2 = log1pf(r2);
                float l3 = log1pf(r3);

                float loc = smooth_l1(pb0 - l0) + smooth_l1(pb1 - l1)
                          + smooth_l1(pb2 - l2) + smooth_l1(pb3 - l3);
                float cm1 = pb4 - 1.0f;
                float nf  = sqrtf(l2 * l3);

                atomicAdd(&d_bacc[b][0], (double)pb4 * (double)pb4);
                atomicAdd(&d_bacc[b][1], (double)cm1 * (double)cm1);
                atomicAdd(&d_bacc[b][2], (double)loc);
                atomicAdd(&d_bacc[b][3], (double)(s / nf));
                atomicAdd(&d_bacc[b][4], 1.0);
                __threadfence();
            }
        }
    }

    // ---- tail: float warp-reduce of conf2, ticket, 5-warp finalize ----
    {
        float x = cs;
#pragma unroll
        for (int o = 16; o > 0; o >>= 1)
            x += __shfl_down_sync(0xffffffffu, x, o);
        if (lane == 0) sh[wid] = (double)x;
        __syncthreads();
        if (threadIdx.x == 0) {
            double s01 = sh[0] + sh[1];
            double s23 = sh[2] + sh[3];
            double s45 = sh[4] + sh[5];
            double s67 = sh[6] + sh[7];
            double sum = (s01 + s23) + (s45 + s67);
            atomicAdd(&d_acc0, sum);
            __threadfence();
            s_last = (atomicAdd(&d_done, 1) == NBLK - 1) ? 1 : 0;
        }
        __syncthreads();

        if (s_last) {
            __threadfence();   // make all blocks' partials visible
            if (wid < 5) {
                double x5 = d_bacc[lane][wid];
#pragma unroll
                for (int o = 16; o > 0; o >>= 1)
                    x5 += __shfl_down_sync(0xffffffffu, x5, o);
                d_bacc[lane][wid] = 0.0;    // reset for next replay
                if (lane == 0) s_out[wid] = x5;
            }
            __syncthreads();
            if (threadIdx.x == 0) {
                double conf2_all = d_acc0;
                double conf2_obj = s_out[0];
                double conf1_obj = s_out[1];
                double loc_sum   = s_out[2];
                double nme_sum   = s_out[3];
                double cnt       = s_out[4];

                double n_obj   = fmax(cnt, 1.0);
                double n_noobj = fmax((double)NCELL - cnt, 1.0);

                out[0] = (float)(2.0 * nme_sum / (68.0 * n_obj));
                out[1] = (float)(5.0 * loc_sum / (n_obj * 4.0));
                out[2] = (float)(0.5 * (conf2_all - conf2_obj) / n_noobj
                                 + conf1_obj / n_obj);

                d_acc0 = 0.0;
                __threadfence();
                d_done = 0;
            }
        }
    }
}

extern "C" void kernel_launch(void* const* d_in, const int* in_sizes, int n_in,
                              void* d_out, int out_size) {
    const float* bbox_pred = (const float*)d_in[0];   // (32,36,36,5,5)
    const float* lm_pred   = (const float*)d_in[1];   // (32,36,36,5,68,2)
    const float* bbox_tgt  = (const float*)d_in[2];   // (32,32,5)
    const float* lm_tgt    = (const float*)d_in[3];   // (32,32,68,2)
    float* out = (float*)d_out;

    fused_kernel<<<NBLK, NTHR>>>(bbox_pred, lm_pred, bbox_tgt, lm_tgt, out);
}